// round 12
// baseline (speedup 1.0000x reference)
#include <cuda_runtime.h>

#define NROWS 256
#define TPB   512

// One block per row: reduce row of conv1 -> mean -> scale row of conv2.
// Zero inter-block communication. 8-way front-batched float4 loads in both
// phases for deep MLP (8 x 128B lines in flight per warp).
__global__ __launch_bounds__(TPB, 2) void fused_row_kernel(const float* __restrict__ c1,
                                                           const float* __restrict__ c2,
                                                           float* __restrict__ out,
                                                           int row_elems) {
    const int row = blockIdx.x;
    const int tid = threadIdx.x;
    const size_t row_base = (size_t)row * row_elems;
    const int n4 = row_elems >> 2;             // 12544 = 3*4096 + 256

    // ---------------- Phase A: reduce conv1[row] ----------------
    const float4* p = reinterpret_cast<const float4*>(c1 + row_base);
    float s0 = 0.f, s1 = 0.f, s2 = 0.f, s3 = 0.f;
    float s4 = 0.f, s5 = 0.f, s6 = 0.f, s7 = 0.f;

    if (n4 == 12544) {
        #pragma unroll
        for (int k = 0; k < 3; k++) {
            const int b = k * 4096 + tid;
            float4 a0 = __ldcs(&p[b]);
            float4 a1 = __ldcs(&p[b + 512]);
            float4 a2 = __ldcs(&p[b + 1024]);
            float4 a3 = __ldcs(&p[b + 1536]);
            float4 a4 = __ldcs(&p[b + 2048]);
            float4 a5 = __ldcs(&p[b + 2560]);
            float4 a6 = __ldcs(&p[b + 3072]);
            float4 a7 = __ldcs(&p[b + 3584]);
            s0 += (a0.x + a0.y) + (a0.z + a0.w);
            s1 += (a1.x + a1.y) + (a1.z + a1.w);
            s2 += (a2.x + a2.y) + (a2.z + a2.w);
            s3 += (a3.x + a3.y) + (a3.z + a3.w);
            s4 += (a4.x + a4.y) + (a4.z + a4.w);
            s5 += (a5.x + a5.y) + (a5.z + a5.w);
            s6 += (a6.x + a6.y) + (a6.z + a6.w);
            s7 += (a7.x + a7.y) + (a7.z + a7.w);
        }
        if (tid < 256) {
            float4 a = __ldcs(&p[12288 + tid]);
            s0 += (a.x + a.y) + (a.z + a.w);
        }
    } else {
        for (int i = tid; i < n4; i += TPB) {
            float4 a = __ldcs(&p[i]);
            s0 += (a.x + a.y) + (a.z + a.w);
        }
    }
    float s = ((s0 + s1) + (s2 + s3)) + ((s4 + s5) + (s6 + s7));

    #pragma unroll
    for (int o = 16; o > 0; o >>= 1)
        s += __shfl_xor_sync(0xffffffffu, s, o);

    __shared__ float warp_sums[16];
    __shared__ float s_mean;
    const int lane = tid & 31;
    const int wid  = tid >> 5;
    if (lane == 0) warp_sums[wid] = s;
    __syncthreads();
    if (tid == 0) {
        float t = 0.f;
        #pragma unroll
        for (int w = 0; w < 16; w++) t += warp_sums[w];  // fixed order: deterministic
        s_mean = t / (float)row_elems;
    }
    __syncthreads();
    const float m = s_mean;

    // ---------------- Phase B: out[row] = m * conv2[row] ----------------
    const float4* src = reinterpret_cast<const float4*>(c2 + row_base);
    float4* dst       = reinterpret_cast<float4*>(out + row_base);

    if (n4 == 12544) {
        #pragma unroll
        for (int k = 0; k < 3; k++) {
            const int b = k * 4096 + tid;
            float4 a0 = __ldcs(&src[b]);
            float4 a1 = __ldcs(&src[b + 512]);
            float4 a2 = __ldcs(&src[b + 1024]);
            float4 a3 = __ldcs(&src[b + 1536]);
            float4 a4 = __ldcs(&src[b + 2048]);
            float4 a5 = __ldcs(&src[b + 2560]);
            float4 a6 = __ldcs(&src[b + 3072]);
            float4 a7 = __ldcs(&src[b + 3584]);
            a0.x *= m; a0.y *= m; a0.z *= m; a0.w *= m;
            a1.x *= m; a1.y *= m; a1.z *= m; a1.w *= m;
            a2.x *= m; a2.y *= m; a2.z *= m; a2.w *= m;
            a3.x *= m; a3.y *= m; a3.z *= m; a3.w *= m;
            a4.x *= m; a4.y *= m; a4.z *= m; a4.w *= m;
            a5.x *= m; a5.y *= m; a5.z *= m; a5.w *= m;
            a6.x *= m; a6.y *= m; a6.z *= m; a6.w *= m;
            a7.x *= m; a7.y *= m; a7.z *= m; a7.w *= m;
            __stcs(&dst[b],        a0);
            __stcs(&dst[b + 512],  a1);
            __stcs(&dst[b + 1024], a2);
            __stcs(&dst[b + 1536], a3);
            __stcs(&dst[b + 2048], a4);
            __stcs(&dst[b + 2560], a5);
            __stcs(&dst[b + 3072], a6);
            __stcs(&dst[b + 3584], a7);
        }
        if (tid < 256) {
            float4 a = __ldcs(&src[12288 + tid]);
            a.x *= m; a.y *= m; a.z *= m; a.w *= m;
            __stcs(&dst[12288 + tid], a);
        }
    } else {
        for (int i = tid; i < n4; i += TPB) {
            float4 a = __ldcs(&src[i]);
            a.x *= m; a.y *= m; a.z *= m; a.w *= m;
            __stcs(&dst[i], a);
        }
    }
}

extern "C" void kernel_launch(void* const* d_in, const int* in_sizes, int n_in,
                              void* d_out, int out_size) {
    const float* c1 = (const float*)d_in[0];
    const float* c2 = (const float*)d_in[1];
    float* out = (float*)d_out;

    const int row_elems = in_sizes[0] / NROWS;  // 50176

    fused_row_kernel<<<NROWS, TPB>>>(c1, c2, out, row_elems);
}

// round 13
// speedup vs baseline: 1.0154x; 1.0154x over previous
#include <cuda_runtime.h>

#define NROWS 256
#define TPB   512

// One block per row: reduce row of conv1 -> mean -> scale row of conv2.
// 6-way front-batched float4 loads: 32 warps/SM x 6 x 128B = 24KB in flight
// per SM (covers ~500cyc DRAM latency at 42.6 B/cyc/SM), while staying inside
// the 64-reg budget of __launch_bounds__(512,2) (no spills, unlike 8-way).
__global__ __launch_bounds__(TPB, 2) void fused_row_kernel(const float* __restrict__ c1,
                                                           const float* __restrict__ c2,
                                                           float* __restrict__ out,
                                                           int row_elems) {
    const int row = blockIdx.x;
    const int tid = threadIdx.x;
    const size_t row_base = (size_t)row * row_elems;
    const int n4 = row_elems >> 2;             // 12544 = 4*3072 + 256

    // ---------------- Phase A: reduce conv1[row] ----------------
    const float4* p = reinterpret_cast<const float4*>(c1 + row_base);
    float s0 = 0.f, s1 = 0.f, s2 = 0.f, s3 = 0.f, s4 = 0.f, s5 = 0.f;

    if (n4 == 12544) {
        #pragma unroll
        for (int k = 0; k < 4; k++) {
            const int b = k * 3072 + tid;
            float4 a0 = __ldcs(&p[b]);
            float4 a1 = __ldcs(&p[b + 512]);
            float4 a2 = __ldcs(&p[b + 1024]);
            float4 a3 = __ldcs(&p[b + 1536]);
            float4 a4 = __ldcs(&p[b + 2048]);
            float4 a5 = __ldcs(&p[b + 2560]);
            s0 += (a0.x + a0.y) + (a0.z + a0.w);
            s1 += (a1.x + a1.y) + (a1.z + a1.w);
            s2 += (a2.x + a2.y) + (a2.z + a2.w);
            s3 += (a3.x + a3.y) + (a3.z + a3.w);
            s4 += (a4.x + a4.y) + (a4.z + a4.w);
            s5 += (a5.x + a5.y) + (a5.z + a5.w);
        }
        if (tid < 256) {
            float4 a = __ldcs(&p[12288 + tid]);
            s0 += (a.x + a.y) + (a.z + a.w);
        }
    } else {
        for (int i = tid; i < n4; i += TPB) {
            float4 a = __ldcs(&p[i]);
            s0 += (a.x + a.y) + (a.z + a.w);
        }
    }
    float s = ((s0 + s1) + (s2 + s3)) + (s4 + s5);

    #pragma unroll
    for (int o = 16; o > 0; o >>= 1)
        s += __shfl_xor_sync(0xffffffffu, s, o);

    __shared__ float warp_sums[16];
    __shared__ float s_mean;
    const int lane = tid & 31;
    const int wid  = tid >> 5;
    if (lane == 0) warp_sums[wid] = s;
    __syncthreads();
    if (tid == 0) {
        float t = 0.f;
        #pragma unroll
        for (int w = 0; w < 16; w++) t += warp_sums[w];  // fixed order: deterministic
        s_mean = t / (float)row_elems;
    }
    __syncthreads();
    const float m = s_mean;

    // ---------------- Phase B: out[row] = m * conv2[row] ----------------
    const float4* src = reinterpret_cast<const float4*>(c2 + row_base);
    float4* dst       = reinterpret_cast<float4*>(out + row_base);

    if (n4 == 12544) {
        #pragma unroll
        for (int k = 0; k < 4; k++) {
            const int b = k * 3072 + tid;
            float4 a0 = __ldcs(&src[b]);
            float4 a1 = __ldcs(&src[b + 512]);
            float4 a2 = __ldcs(&src[b + 1024]);
            float4 a3 = __ldcs(&src[b + 1536]);
            float4 a4 = __ldcs(&src[b + 2048]);
            float4 a5 = __ldcs(&src[b + 2560]);
            a0.x *= m; a0.y *= m; a0.z *= m; a0.w *= m;
            a1.x *= m; a1.y *= m; a1.z *= m; a1.w *= m;
            a2.x *= m; a2.y *= m; a2.z *= m; a2.w *= m;
            a3.x *= m; a3.y *= m; a3.z *= m; a3.w *= m;
            a4.x *= m; a4.y *= m; a4.z *= m; a4.w *= m;
            a5.x *= m; a5.y *= m; a5.z *= m; a5.w *= m;
            __stcs(&dst[b],        a0);
            __stcs(&dst[b + 512],  a1);
            __stcs(&dst[b + 1024], a2);
            __stcs(&dst[b + 1536], a3);
            __stcs(&dst[b + 2048], a4);
            __stcs(&dst[b + 2560], a5);
        }
        if (tid < 256) {
            float4 a = __ldcs(&src[12288 + tid]);
            a.x *= m; a.y *= m; a.z *= m; a.w *= m;
            __stcs(&dst[12288 + tid], a);
        }
    } else {
        for (int i = tid; i < n4; i += TPB) {
            float4 a = __ldcs(&src[i]);
            a.x *= m; a.y *= m; a.z *= m; a.w *= m;
            __stcs(&dst[i], a);
        }
    }
}

extern "C" void kernel_launch(void* const* d_in, const int* in_sizes, int n_in,
                              void* d_out, int out_size) {
    const float* c1 = (const float*)d_in[0];
    const float* c2 = (const float*)d_in[1];
    float* out = (float*)d_out;

    const int row_elems = in_sizes[0] / NROWS;  // 50176

    fused_row_kernel<<<NROWS, TPB>>>(c1, c2, out, row_elems);
}